// round 9
// baseline (speedup 1.0000x reference)
#include <cuda_runtime.h>
#include <cuda_bf16.h>
#include <math.h>
#include <stdint.h>

#define BB 2
#define SS 4096
#define DD 1024
#define HH 16
#define DH 64
#define WW 256
#define MM (BB * SS)

// ---------------- device scratch (allocation-free rule) ----------------
__device__ uint32_t g_xt[MM * DD];          // x (then ao) in tf32, A-fragment-major
__device__ uint32_t g_wt[4 * DD * DD];      // wq,wk,wv,wo in tf32, B-fragment-major
__device__ float g_ao[MM * DD];             // attention output, fp32
__device__ __nv_bfloat16 g_qh[MM * DD];
__device__ __nv_bfloat16 g_ql[MM * DD];
__device__ __nv_bfloat16 g_kh[MM * DD];
__device__ __nv_bfloat16 g_kl[MM * DD];
__device__ __nv_bfloat16 g_vh[MM * DD];
__device__ __nv_bfloat16 g_vl[MM * DD];

// ---------------- family-portable PTX helpers ----------------
__device__ __forceinline__ uint32_t smem_u32(const void* p) {
    uint32_t a;
    asm("{ .reg .u64 t; cvta.to.shared.u64 t, %1; cvt.u32.u64 %0, t; }"
        : "=r"(a) : "l"(p));
    return a;
}
__device__ __forceinline__ uint32_t f2tf32(float f) {
    uint32_t u;
    asm("cvt.rna.tf32.f32 %0, %1;" : "=r"(u) : "f"(f));
    return u;
}

#define LDSM4(r0, r1, r2, r3, addr)                                              \
    asm volatile("ldmatrix.sync.aligned.m8n8.x4.shared.b16 {%0,%1,%2,%3}, [%4];"  \
                 : "=r"(r0), "=r"(r1), "=r"(r2), "=r"(r3) : "r"(addr))
#define LDSM4T(r0, r1, r2, r3, addr)                                             \
    asm volatile("ldmatrix.sync.aligned.m8n8.x4.trans.shared.b16 {%0,%1,%2,%3}, [%4];" \
                 : "=r"(r0), "=r"(r1), "=r"(r2), "=r"(r3) : "r"(addr))
#define LDS128U(r, addr)                                                         \
    asm volatile("ld.shared.v4.b32 {%0,%1,%2,%3}, [%4];"                          \
                 : "=r"((r)[0]), "=r"((r)[1]), "=r"((r)[2]), "=r"((r)[3])         \
                 : "r"(addr))
#define LDS64U(r, addr)                                                          \
    asm volatile("ld.shared.v2.b32 {%0,%1}, [%2];"                                \
                 : "=r"((r)[0]), "=r"((r)[1]) : "r"(addr))

#define MMA16816(d, a, b)                                                        \
    asm volatile(                                                                \
        "mma.sync.aligned.m16n8k16.row.col.f32.bf16.bf16.f32 "                   \
        "{%0,%1,%2,%3},{%4,%5,%6,%7},{%8,%9},{%0,%1,%2,%3};"                     \
        : "+f"((d)[0]), "+f"((d)[1]), "+f"((d)[2]), "+f"((d)[3])                 \
        : "r"((a)[0]), "r"((a)[1]), "r"((a)[2]), "r"((a)[3]),                    \
          "r"((b)[0]), "r"((b)[1]))
#define MMATF32(d, a, b)                                                         \
    asm volatile(                                                                \
        "mma.sync.aligned.m16n8k8.row.col.f32.tf32.tf32.f32 "                    \
        "{%0,%1,%2,%3},{%4,%5,%6,%7},{%8,%9},{%0,%1,%2,%3};"                     \
        : "+f"((d)[0]), "+f"((d)[1]), "+f"((d)[2]), "+f"((d)[3])                 \
        : "r"((a)[0]), "r"((a)[1]), "r"((a)[2]), "r"((a)[3]),                    \
          "r"((b)[0]), "r"((b)[1]))

#define CPASYNC16Z(dst, src, sz)                                                 \
    asm volatile("cp.async.cg.shared.global [%0], [%1], 16, %2;"                  \
                 :: "r"(dst), "l"(src), "r"(sz))
#define CPCOMMIT() asm volatile("cp.async.commit_group;" ::: "memory")
#define CPWAIT0()  asm volatile("cp.async.wait_group 0;" ::: "memory")
#define CPWAIT1()  asm volatile("cp.async.wait_group 1;" ::: "memory")

// --- bulk async copy + mbarrier (sm_90 baseline, family-portable) ---
#define MBAR_INIT(a, c)                                                          \
    asm volatile("mbarrier.init.shared.b64 [%0], %1;" :: "r"(a), "r"(c) : "memory")
#define MBAR_EXPECT(a, bytes)                                                    \
    asm volatile("mbarrier.arrive.expect_tx.shared.b64 _, [%0], %1;"              \
                 :: "r"(a), "r"(bytes) : "memory")
#define BULKCP(dst, src, sz, mb)                                                 \
    asm volatile("cp.async.bulk.shared::cta.global.mbarrier::complete_tx::bytes " \
                 "[%0], [%1], %2, [%3];"                                          \
                 :: "r"(dst), "l"(src), "r"(sz), "r"(mb) : "memory")
#define MBAR_WAIT(a, p)                                                          \
    asm volatile(                                                                \
        "{\n\t.reg .pred P;\n\t"                                                 \
        "W_%=:\n\t"                                                              \
        "mbarrier.try_wait.parity.acquire.cta.shared::cta.b64 P, [%0], %1;\n\t"  \
        "@P bra.uni D_%=;\n\t"                                                   \
        "bra.uni W_%=;\n\t"                                                      \
        "D_%=:\n\t}"                                                             \
        :: "r"(a), "r"(p) : "memory")

#define PSPLIT(ph, pl, va, vb)                                                   \
    {                                                                            \
        __nv_bfloat162 _h = __float22bfloat162_rn(make_float2((va), (vb)));      \
        float _ra = (va) - __bfloat162float(__low2bfloat16(_h));                 \
        float _rb = (vb) - __bfloat162float(__high2bfloat16(_h));                \
        __nv_bfloat162 _l = __float22bfloat162_rn(make_float2(_ra, _rb));        \
        (ph) = *(uint32_t*)&_h;                                                  \
        (pl) = *(uint32_t*)&_l;                                                  \
    }

extern __shared__ char dynsm[];

// ---------------------------------------------------------------------------
// Converters to tf32 fragment-major layouts.
// ---------------------------------------------------------------------------
__global__ __launch_bounds__(256) void conv_a_tf32(const float* __restrict__ x,
                                                   uint32_t* __restrict__ out) {
    int i = (blockIdx.x * 256 + threadIdx.x) * 4;
    float4 v = *(const float4*)(x + i);
    float f[4] = {v.x, v.y, v.z, v.w};
    int r = i >> 10, c = i & 1023;
    int rb = r >> 4, ri = r & 15, kb = c >> 3;
    int jj = (ri >> 3) + 2 * ((c & 7) >> 2);
    uint32_t* o = out + ((size_t)(rb * 128 + kb) << 7) + jj;
    int lane0 = (ri & 7) * 4;
#pragma unroll
    for (int m = 0; m < 4; m++) o[(lane0 + m) << 2] = f2tf32(f[m]);
}

__global__ __launch_bounds__(256) void conv_b_tf32(const float* __restrict__ w0,
                                                   const float* __restrict__ w1,
                                                   const float* __restrict__ w2,
                                                   const float* __restrict__ w3,
                                                   uint32_t* __restrict__ out) {
    const int z = blockIdx.y;
    const float* w = (z == 0) ? w0 : (z == 1) ? w1 : (z == 2) ? w2 : w3;
    uint32_t* ob = out + (size_t)z * DD * DD;
    int i = (blockIdx.x * 256 + threadIdx.x) * 4;
    float4 v = *(const float4*)(w + i);
    float f[4] = {v.x, v.y, v.z, v.w};
    int n = i >> 10, k = i & 1023;
    int nb = n >> 3, ni = n & 7, kb = k >> 3;
    int j = (k & 7) >> 2;
    uint32_t* o = ob + ((size_t)(nb * 128 + kb) << 6) + j;
    int lane0 = ni * 4;
#pragma unroll
    for (int m = 0; m < 4; m++) o[(lane0 + m) << 1] = f2tf32(f[m]);
}

// ---------------------------------------------------------------------------
// tf32 GEMM mainloop: 128x128 tile, BK=32, 3-stage bulk-copy ring.
// 128 threads = 4 warps in a 2m x 2n grid, warp tile 64x64 (mf=4, nf=8).
// smem bytes/MMA = 125 (was 192) -> tensor-issue bound instead of smem-BW.
// ---------------------------------------------------------------------------
#define T32_STAGE 32768

__device__ __forceinline__ void tf32_mainloop(const uint32_t* A0, const uint32_t* B0,
                                              uint32_t sb, int t, int lane,
                                              int warp_m, int warp_n,
                                              float acc[4][8][4]) {
    __shared__ __align__(8) unsigned long long mbars[3];
    const uint32_t mb = smem_u32(mbars);

    if (t == 0) {
        MBAR_INIT(mb + 0, 1);
        MBAR_INIT(mb + 8, 1);
        MBAR_INIT(mb + 16, 1);
    }
    __syncthreads();

    auto issue = [&](int s, int buf) {
        const uint32_t base = sb + buf * T32_STAGE;
        const uint32_t m = mb + buf * 8;
        const int kb0 = s * 4;
        MBAR_EXPECT(m, 32768u);
#pragma unroll
        for (int rbl = 0; rbl < 8; rbl++)
            BULKCP(base + rbl * 2048, A0 + (((rbl << 7) + kb0) << 7), 2048u, m);
#pragma unroll
        for (int nbl = 0; nbl < 16; nbl++)
            BULKCP(base + 16384 + nbl * 1024, B0 + (((nbl << 7) + kb0) << 6), 1024u, m);
    };

    if (t == 0) { issue(0, 0); issue(1, 1); }

    for (int s = 0; s < 32; s++) {
        const int buf = s - (s / 3) * 3;          // s % 3
        const int par = (s / 3) & 1;
        MBAR_WAIT(mb + buf * 8, par);
        __syncthreads();                          // all warps done reading buf (s+2)%3
        if (t == 0 && s + 2 < 32) issue(s + 2, (s + 2) % 3);

        const uint32_t sA = sb + buf * T32_STAGE;
        const uint32_t sB = sA + 16384;

#pragma unroll
        for (int ksp = 0; ksp < 2; ksp++) {
            const int ks0 = ksp * 2;
            // B fragments for this ks-pair: 16 LDS.64 (conflict-free)
            uint32_t bf[2][8][2];
#pragma unroll
            for (int kk = 0; kk < 2; kk++)
#pragma unroll
                for (int nf = 0; nf < 8; nf++)
                    LDS64U(bf[kk][nf],
                           sB + ((((warp_n * 8 + nf) << 2) + ks0 + kk) << 8) + lane * 8);

            // A: register double-buffer over 8 (mf, kk) iterations
            uint32_t ap[2][4];
            LDS128U(ap[0], sA + ((((warp_m * 4) << 2) + ks0) << 9) + lane * 16);
#pragma unroll
            for (int it = 0; it < 8; it++) {
                const int mf = it >> 1, kk = it & 1;
                if (it < 7) {
                    const int nmf = (it + 1) >> 1, nkk = (it + 1) & 1;
                    LDS128U(ap[(it + 1) & 1],
                            sA + ((((warp_m * 4 + nmf) << 2) + ks0 + nkk) << 9) + lane * 16);
                }
#pragma unroll
                for (int nf = 0; nf < 8; nf++)
                    MMATF32(acc[mf][nf], ap[it & 1], bf[kk][nf]);
            }
        }
    }
}

// QKV: split-bf16 epilogue (Q scaled by 0.125)
__global__ __launch_bounds__(128, 2)
void tgemm32(const uint32_t* __restrict__ At, const uint32_t* __restrict__ Wt,
             __nv_bfloat16* __restrict__ Ch0, __nv_bfloat16* __restrict__ Cl0,
             __nv_bfloat16* __restrict__ Ch1, __nv_bfloat16* __restrict__ Cl1,
             __nv_bfloat16* __restrict__ Ch2, __nv_bfloat16* __restrict__ Cl2) {
    const int t = threadIdx.x;
    const int lane = t & 31;
    const int wid = t >> 5;
    const int warp_m = wid >> 1, warp_n = wid & 1;
    const int z = blockIdx.z;
    const uint32_t sb = smem_u32(dynsm);

    const uint32_t* A0 = At + ((size_t)(blockIdx.y * 8) << 14);
    const uint32_t* B0 = Wt + (size_t)z * DD * DD + ((size_t)(blockIdx.x * 16) << 13);

    float acc[4][8][4];
#pragma unroll
    for (int i = 0; i < 4; i++)
#pragma unroll
        for (int j = 0; j < 8; j++)
#pragma unroll
            for (int r = 0; r < 4; r++) acc[i][j][r] = 0.f;

    tf32_mainloop(A0, B0, sb, t, lane, warp_m, warp_n, acc);

    __nv_bfloat16* Ch = (z == 0) ? Ch0 : (z == 1) ? Ch1 : Ch2;
    __nv_bfloat16* Cl = (z == 0) ? Cl0 : (z == 1) ? Cl1 : Cl2;
    const float scale = (z == 0) ? 0.125f : 1.0f;
    const int bm = blockIdx.y << 7, bn = blockIdx.x << 7;
#pragma unroll
    for (int mf = 0; mf < 4; mf++) {
        const int r0 = bm + warp_m * 64 + mf * 16 + (lane >> 2);
#pragma unroll
        for (int nf = 0; nf < 8; nf++) {
            const int cn = bn + warp_n * 64 + nf * 8 + (lane & 3) * 2;
#pragma unroll
            for (int hh = 0; hh < 2; hh++) {
                float v0 = acc[mf][nf][hh * 2 + 0] * scale;
                float v1 = acc[mf][nf][hh * 2 + 1] * scale;
                uint32_t ph, pl;
                PSPLIT(ph, pl, v0, v1);
                size_t off = (size_t)(r0 + hh * 8) * DD + cn;
                *(uint32_t*)&Ch[off] = ph;
                *(uint32_t*)&Cl[off] = pl;
            }
        }
    }
}

// O projection: fp32 epilogue
__global__ __launch_bounds__(128, 2)
void tgemm32f(const uint32_t* __restrict__ At, const uint32_t* __restrict__ Wt,
              float* __restrict__ C) {
    const int t = threadIdx.x;
    const int lane = t & 31;
    const int wid = t >> 5;
    const int warp_m = wid >> 1, warp_n = wid & 1;
    const uint32_t sb = smem_u32(dynsm);

    const uint32_t* A0 = At + ((size_t)(blockIdx.y * 8) << 14);
    const uint32_t* B0 = Wt + ((size_t)(blockIdx.x * 16) << 13);

    float acc[4][8][4];
#pragma unroll
    for (int i = 0; i < 4; i++)
#pragma unroll
        for (int j = 0; j < 8; j++)
#pragma unroll
            for (int r = 0; r < 4; r++) acc[i][j][r] = 0.f;

    tf32_mainloop(A0, B0, sb, t, lane, warp_m, warp_n, acc);

    const int bm = blockIdx.y << 7, bn = blockIdx.x << 7;
#pragma unroll
    for (int mf = 0; mf < 4; mf++) {
        const int r0 = bm + warp_m * 64 + mf * 16 + (lane >> 2);
#pragma unroll
        for (int nf = 0; nf < 8; nf++) {
            const int cn = bn + warp_n * 64 + nf * 8 + (lane & 3) * 2;
            *(float2*)&C[(size_t)r0 * DD + cn] =
                make_float2(acc[mf][nf][0], acc[mf][nf][1]);
            *(float2*)&C[(size_t)(r0 + 8) * DD + cn] =
                make_float2(acc[mf][nf][2], acc[mf][nf][3]);
        }
    }
}

// ---------------------------------------------------------------------------
// Tensor-core sliding-window flash attention; fp32 output. (unchanged)
// ---------------------------------------------------------------------------
#define APITCH 144
#define ATILE (64 * APITCH)
#define ABUF  (4 * ATILE)

__global__ __launch_bounds__(256, 1)
void swa_mma(const __nv_bfloat16* __restrict__ Qh, const __nv_bfloat16* __restrict__ Ql,
             const __nv_bfloat16* __restrict__ Kh, const __nv_bfloat16* __restrict__ Kl,
             const __nv_bfloat16* __restrict__ Vh, const __nv_bfloat16* __restrict__ Vl,
             float* __restrict__ O) {
    const int jq = blockIdx.x, h = blockIdx.y, b = blockIdx.z;
    const int t = threadIdx.x, lane = t & 31, wid = t >> 5;
    const int tq = wid * 16;
    const uint32_t sb = smem_u32(dynsm);
    const int kv0 = 128 * jq - 256;

    uint32_t qA[2][4][4];
    {
        const int r0 = 128 * jq + tq + (lane >> 2);
        const size_t rowb = (size_t)(b * SS + r0) * DD + h * DH + 2 * (lane & 3);
        const __nv_bfloat16* Qs[2] = {Qh, Ql};
#pragma unroll
        for (int term = 0; term < 2; term++)
#pragma unroll
            for (int kf = 0; kf < 4; kf++) {
                qA[term][kf][0] = *(const uint32_t*)(Qs[term] + rowb + kf * 16);
                qA[term][kf][1] = *(const uint32_t*)(Qs[term] + rowb + 8 * DD + kf * 16);
                qA[term][kf][2] = *(const uint32_t*)(Qs[term] + rowb + kf * 16 + 8);
                qA[term][kf][3] = *(const uint32_t*)(Qs[term] + rowb + 8 * DD + kf * 16 + 8);
            }
    }

    const __nv_bfloat16* srcs[4] = {Kh, Kl, Vh, Vl};
    auto load_chunk = [&](int c, int buf) {
        const int kbase = kv0 + 64 * c;
#pragma unroll
        for (int it = 0; it < 8; it++) {
            int idx = t + it * 256;
            int tensor = idx >> 9;
            int row = (idx >> 3) & 63;
            int dch = idx & 7;
            int kp = kbase + row;
            int ok = (kp >= 0) ? 16 : 0;
            int kpc = kp >= 0 ? kp : 0;
            uint32_t dst = sb + buf * ABUF + tensor * ATILE + row * APITCH + dch * 16;
            const void* src = srcs[tensor] + (size_t)(b * SS + kpc) * DD + h * DH + dch * 8;
            CPASYNC16Z(dst, src, ok);
        }
    };

    float o[8][4];
#pragma unroll
    for (int nf = 0; nf < 8; nf++)
#pragma unroll
        for (int r = 0; r < 4; r++) o[nf][r] = 0.f;
    float m0 = -1e30f, m1 = -1e30f, lp0 = 0.f, lp1 = 0.f;

    const int cmin = (tq + 1) >> 6;
    const int cmax = (tq + 271) >> 6;

    load_chunk(0, 0);
    CPCOMMIT();

    for (int c = 0; c < 6; c++) {
        if (c < 5) {
            load_chunk(c + 1, (c + 1) & 1);
            CPCOMMIT();
            CPWAIT1();
        } else {
            CPWAIT0();
        }
        __syncthreads();

        const int kbase = kv0 + 64 * c;
        if (c >= cmin && c <= cmax && kbase + 63 >= 0) {
            const uint32_t kvb = sb + (c & 1) * ABUF;

            float s[8][4];
#pragma unroll
            for (int nf = 0; nf < 8; nf++)
#pragma unroll
                for (int r = 0; r < 4; r++) s[nf][r] = 0.f;

#pragma unroll
            for (int kf = 0; kf < 4; kf++) {
#pragma unroll
                for (int kg = 0; kg < 4; kg++) {
                    uint32_t addr = kvb +
                        (kg * 16 + (lane & 7) + ((lane >> 4) << 3)) * APITCH +
                        ((lane >> 3) & 1) * 16 + kf * 32;
                    uint32_t bh[4], bl[4];
                    LDSM4(bh[0], bh[1], bh[2], bh[3], addr);
                    LDSM4(bl[0], bl[1], bl[2], bl[3], addr + ATILE);
                    MMA16816(s[2 * kg],     qA[0][kf], &bh[0]);
                    MMA16816(s[2 * kg],     qA[0][kf], &bl[0]);
                    MMA16816(s[2 * kg],     qA[1][kf], &bh[0]);
                    MMA16816(s[2 * kg + 1], qA[0][kf], &bh[2]);
                    MMA16816(s[2 * kg + 1], qA[0][kf], &bl[2]);
                    MMA16816(s[2 * kg + 1], qA[1][kf], &bh[2]);
                }
            }

            {
                const int qg = 128 * jq + tq + (lane >> 2);
                const int d0 = qg - (kbase + 2 * (lane & 3));
#pragma unroll
                for (int nf = 0; nf < 8; nf++) {
                    int e = d0 - nf * 8;
                    s[nf][0] = ((unsigned)e <= 255u)       ? s[nf][0] : -1e30f;
                    s[nf][1] = ((unsigned)(e - 1) <= 255u) ? s[nf][1] : -1e30f;
                    s[nf][2] = ((unsigned)(e + 8) <= 255u) ? s[nf][2] : -1e30f;
                    s[nf][3] = ((unsigned)(e + 7) <= 255u) ? s[nf][3] : -1e30f;
                }
            }

            float mx0 = -1e30f, mx1 = -1e30f;
#pragma unroll
            for (int nf = 0; nf < 8; nf++) {
                mx0 = fmaxf(mx0, fmaxf(s[nf][0], s[nf][1]));
                mx1 = fmaxf(mx1, fmaxf(s[nf][2], s[nf][3]));
            }
            mx0 = fmaxf(mx0, __shfl_xor_sync(0xffffffffu, mx0, 1));
            mx0 = fmaxf(mx0, __shfl_xor_sync(0xffffffffu, mx0, 2));
            mx1 = fmaxf(mx1, __shfl_xor_sync(0xffffffffu, mx1, 1));
            mx1 = fmaxf(mx1, __shfl_xor_sync(0xffffffffu, mx1, 2));

            float mn0 = fmaxf(m0, mx0), mn1 = fmaxf(m1, mx1);
            float c0 = __expf(m0 - mn0), c1 = __expf(m1 - mn1);
            m0 = mn0; m1 = mn1;

            float ls0 = 0.f, ls1 = 0.f;
#pragma unroll
            for (int nf = 0; nf < 8; nf++) {
                s[nf][0] = __expf(s[nf][0] - mn0);
                s[nf][1] = __expf(s[nf][1] - mn0);
                s[nf][2] = __expf(s[nf][2] - mn1);
                s[nf][3] = __expf(s[nf][3] - mn1);
                ls0 += s[nf][0] + s[nf][1];
                ls1 += s[nf][2] + s[nf][3];
            }
            lp0 = lp0 * c0 + ls0;
            lp1 = lp1 * c1 + ls1;
#pragma unroll
            for (int nf = 0; nf < 8; nf++) {
                o[nf][0] *= c0; o[nf][1] *= c0;
                o[nf][2] *= c1; o[nf][3] *= c1;
            }

#pragma unroll
            for (int kf = 0; kf < 4; kf++) {
                uint32_t pha[4], pla[4];
                PSPLIT(pha[0], pla[0], s[2 * kf][0], s[2 * kf][1]);
                PSPLIT(pha[1], pla[1], s[2 * kf][2], s[2 * kf][3]);
                PSPLIT(pha[2], pla[2], s[2 * kf + 1][0], s[2 * kf + 1][1]);
                PSPLIT(pha[3], pla[3], s[2 * kf + 1][2], s[2 * kf + 1][3]);
#pragma unroll
                for (int dg = 0; dg < 4; dg++) {
                    uint32_t vaddr = kvb + 2 * ATILE +
                        (kf * 16 + (lane & 15)) * APITCH + dg * 32 +
                        ((lane >> 4) & 1) * 16;
                    uint32_t vh4[4], vl4[4];
                    LDSM4T(vh4[0], vh4[1], vh4[2], vh4[3], vaddr);
                    LDSM4T(vl4[0], vl4[1], vl4[2], vl4[3], vaddr + ATILE);
                    MMA16816(o[2 * dg],     pha, &vh4[0]);
                    MMA16816(o[2 * dg],     pha, &vl4[0]);
                    MMA16816(o[2 * dg],     pla, &vh4[0]);
                    MMA16816(o[2 * dg + 1], pha, &vh4[2]);
                    MMA16816(o[2 * dg + 1], pha, &vl4[2]);
                    MMA16816(o[2 * dg + 1], pla, &vh4[2]);
                }
            }
        }
        __syncthreads();
    }

    lp0 += __shfl_xor_sync(0xffffffffu, lp0, 1);
    lp0 += __shfl_xor_sync(0xffffffffu, lp0, 2);
    lp1 += __shfl_xor_sync(0xffffffffu, lp1, 1);
    lp1 += __shfl_xor_sync(0xffffffffu, lp1, 2);
    const float inv0 = 1.f / lp0, inv1 = 1.f / lp1;

    const int r0 = 128 * jq + tq + (lane >> 2);
    const size_t ob = (size_t)(b * SS + r0) * DD + h * DH + 2 * (lane & 3);
#pragma unroll
    for (int nf = 0; nf < 8; nf++) {
        *(float2*)&O[ob + nf * 8] = make_float2(o[nf][0] * inv0, o[nf][1] * inv0);
        *(float2*)&O[ob + 8 * DD + nf * 8] = make_float2(o[nf][2] * inv1, o[nf][3] * inv1);
    }
}

// ---------------------------------------------------------------------------
extern "C" void kernel_launch(void* const* d_in, const int* in_sizes, int n_in,
                              void* d_out, int out_size) {
    const float* x = (const float*)d_in[0];
    const float* w[4] = {(const float*)d_in[1], (const float*)d_in[2],
                         (const float*)d_in[3], (const float*)d_in[4]};
    float* out = (float*)d_out;

    uint32_t *xt, *wt;
    float* ao;
    __nv_bfloat16 *qh, *ql, *kh, *kl, *vh, *vl;
    cudaGetSymbolAddress((void**)&xt, g_xt);
    cudaGetSymbolAddress((void**)&wt, g_wt);
    cudaGetSymbolAddress((void**)&ao, g_ao);
    cudaGetSymbolAddress((void**)&qh, g_qh);
    cudaGetSymbolAddress((void**)&ql, g_ql);
    cudaGetSymbolAddress((void**)&kh, g_kh);
    cudaGetSymbolAddress((void**)&kl, g_kl);
    cudaGetSymbolAddress((void**)&vh, g_vh);
    cudaGetSymbolAddress((void**)&vl, g_vl);

    const int DYNSM_T = 3 * T32_STAGE;    // 98304
    const int DYNSM_A = 2 * ABUF;         // 73728
    cudaFuncSetAttribute(tgemm32,  cudaFuncAttributeMaxDynamicSharedMemorySize, DYNSM_T);
    cudaFuncSetAttribute(tgemm32f, cudaFuncAttributeMaxDynamicSharedMemorySize, DYNSM_T);
    cudaFuncSetAttribute(swa_mma,  cudaFuncAttributeMaxDynamicSharedMemorySize, DYNSM_A);

    conv_a_tf32<<<(MM * DD) / 1024, 256>>>(x, xt);
    conv_b_tf32<<<dim3((DD * DD) / 1024, 4), 256>>>(w[0], w[1], w[2], w[3], wt);

    dim3 gq(DD / 128, MM / 128, 3);   // (8, 64, 3)
    tgemm32<<<gq, 128, DYNSM_T>>>(xt, wt, qh, ql, kh, kl, vh, vl);

    dim3 ga(SS / 128, HH, BB);        // (32, 16, 2)
    swa_mma<<<ga, 256, DYNSM_A>>>(qh, ql, kh, kl, vh, vl, ao);

    // reuse xt for ao in fragment-major tf32 (x is dead after QKV GEMM)
    conv_a_tf32<<<(MM * DD) / 1024, 256>>>(ao, xt);

    dim3 go(DD / 128, MM / 128);      // (8, 64)
    tgemm32f<<<go, 128, DYNSM_T>>>(xt, wt + 3 * (size_t)DD * DD, out);
}

// round 10
// speedup vs baseline: 1.5596x; 1.5596x over previous
#include <cuda_runtime.h>
#include <cuda_bf16.h>
#include <cuda_fp16.h>
#include <math.h>
#include <stdint.h>

#define BB 2
#define SS 4096
#define DD 1024
#define HH 16
#define DH 64
#define WW 256
#define MM (BB * SS)

// ---------------- device scratch (allocation-free rule) ----------------
__device__ uint32_t g_xt[MM * DD / 2];      // x (then ao) in fp16, A-fragment-major
__device__ uint32_t g_wt[2 * DD * DD];      // wq,wk,wv,wo in fp16, B-fragment-major
__device__ float g_ao[MM * DD];             // attention output, fp32
__device__ __nv_bfloat16 g_qh[MM * DD];
__device__ __nv_bfloat16 g_ql[MM * DD];
__device__ __nv_bfloat16 g_kh[MM * DD];
__device__ __nv_bfloat16 g_kl[MM * DD];
__device__ __nv_bfloat16 g_vh[MM * DD];
__device__ __nv_bfloat16 g_vl[MM * DD];

// W matrix stride in u32 (fp16 fragment-major): DD*DD/2
#define WSTRIDE (DD * DD / 2)

// ---------------- family-portable PTX helpers ----------------
__device__ __forceinline__ uint32_t smem_u32(const void* p) {
    uint32_t a;
    asm("{ .reg .u64 t; cvta.to.shared.u64 t, %1; cvt.u32.u64 %0, t; }"
        : "=r"(a) : "l"(p));
    return a;
}

#define LDSM4(r0, r1, r2, r3, addr)                                              \
    asm volatile("ldmatrix.sync.aligned.m8n8.x4.shared.b16 {%0,%1,%2,%3}, [%4];"  \
                 : "=r"(r0), "=r"(r1), "=r"(r2), "=r"(r3) : "r"(addr))
#define LDSM4T(r0, r1, r2, r3, addr)                                             \
    asm volatile("ldmatrix.sync.aligned.m8n8.x4.trans.shared.b16 {%0,%1,%2,%3}, [%4];" \
                 : "=r"(r0), "=r"(r1), "=r"(r2), "=r"(r3) : "r"(addr))
#define LDS128U(r, addr)                                                         \
    asm volatile("ld.shared.v4.b32 {%0,%1,%2,%3}, [%4];"                          \
                 : "=r"((r)[0]), "=r"((r)[1]), "=r"((r)[2]), "=r"((r)[3])         \
                 : "r"(addr))
#define LDS64U(r, addr)                                                          \
    asm volatile("ld.shared.v2.b32 {%0,%1}, [%2];"                                \
                 : "=r"((r)[0]), "=r"((r)[1]) : "r"(addr))

#define MMA16816(d, a, b)                                                        \
    asm volatile(                                                                \
        "mma.sync.aligned.m16n8k16.row.col.f32.bf16.bf16.f32 "                   \
        "{%0,%1,%2,%3},{%4,%5,%6,%7},{%8,%9},{%0,%1,%2,%3};"                     \
        : "+f"((d)[0]), "+f"((d)[1]), "+f"((d)[2]), "+f"((d)[3])                 \
        : "r"((a)[0]), "r"((a)[1]), "r"((a)[2]), "r"((a)[3]),                    \
          "r"((b)[0]), "r"((b)[1]))
#define MMAF16(d, a, b)                                                          \
    asm volatile(                                                                \
        "mma.sync.aligned.m16n8k16.row.col.f32.f16.f16.f32 "                     \
        "{%0,%1,%2,%3},{%4,%5,%6,%7},{%8,%9},{%0,%1,%2,%3};"                     \
        : "+f"((d)[0]), "+f"((d)[1]), "+f"((d)[2]), "+f"((d)[3])                 \
        : "r"((a)[0]), "r"((a)[1]), "r"((a)[2]), "r"((a)[3]),                    \
          "r"((b)[0]), "r"((b)[1]))

#define CPASYNC16Z(dst, src, sz)                                                 \
    asm volatile("cp.async.cg.shared.global [%0], [%1], 16, %2;"                  \
                 :: "r"(dst), "l"(src), "r"(sz))
#define CPCOMMIT() asm volatile("cp.async.commit_group;" ::: "memory")
#define CPWAIT0()  asm volatile("cp.async.wait_group 0;" ::: "memory")
#define CPWAIT1()  asm volatile("cp.async.wait_group 1;" ::: "memory")

// --- bulk async copy + mbarrier (sm_90 baseline, family-portable) ---
#define MBAR_INIT(a, c)                                                          \
    asm volatile("mbarrier.init.shared.b64 [%0], %1;" :: "r"(a), "r"(c) : "memory")
#define MBAR_EXPECT(a, bytes)                                                    \
    asm volatile("mbarrier.arrive.expect_tx.shared.b64 _, [%0], %1;"              \
                 :: "r"(a), "r"(bytes) : "memory")
#define BULKCP(dst, src, sz, mb)                                                 \
    asm volatile("cp.async.bulk.shared::cta.global.mbarrier::complete_tx::bytes " \
                 "[%0], [%1], %2, [%3];"                                          \
                 :: "r"(dst), "l"(src), "r"(sz), "r"(mb) : "memory")
#define MBAR_WAIT(a, p)                                                          \
    asm volatile(                                                                \
        "{\n\t.reg .pred P;\n\t"                                                 \
        "W_%=:\n\t"                                                              \
        "mbarrier.try_wait.parity.acquire.cta.shared::cta.b64 P, [%0], %1;\n\t"  \
        "@P bra.uni D_%=;\n\t"                                                   \
        "bra.uni W_%=;\n\t"                                                      \
        "D_%=:\n\t}"                                                             \
        :: "r"(a), "r"(p) : "memory")

#define PSPLIT(ph, pl, va, vb)                                                   \
    {                                                                            \
        __nv_bfloat162 _h = __float22bfloat162_rn(make_float2((va), (vb)));      \
        float _ra = (va) - __bfloat162float(__low2bfloat16(_h));                 \
        float _rb = (vb) - __bfloat162float(__high2bfloat16(_h));                \
        __nv_bfloat162 _l = __float22bfloat162_rn(make_float2(_ra, _rb));        \
        (ph) = *(uint32_t*)&_h;                                                  \
        (pl) = *(uint32_t*)&_l;                                                  \
    }

extern __shared__ char dynsm[];

// ---------------------------------------------------------------------------
// Converters to fp16 fragment-major layouts (m16n8k16).
// A block (16 rows x 16 cols) = 128 u32: idx = lane*4 + reg
//   lane = (ri&7)*4 + ((ci&7)>>1); reg = (ri>>3) + 2*((ci&15)>>3); half = ci&1
// B block (8 n x 16 k) = 64 u32: idx = lane*2 + reg
//   lane = ni*4 + ((ki&7)>>1); reg = (ki&15)>>3; half = ki&1
// ---------------------------------------------------------------------------
__global__ __launch_bounds__(256) void conv_a_f16(const float* __restrict__ x,
                                                  uint32_t* __restrict__ out) {
    int i = (blockIdx.x * 256 + threadIdx.x) * 4;
    float4 v = *(const float4*)(x + i);
    int r = i >> 10, c = i & 1023;
    int rb = r >> 4, ri = r & 15, kb = c >> 4;
    int reg = (ri >> 3) + 2 * ((c & 15) >> 3);       // same for all 4 cols
    int lane0 = (ri & 7) * 4 + ((c & 7) >> 1);
    uint32_t* o = out + ((size_t)(rb * 64 + kb) << 7);
    __half2 h01 = __floats2half2_rn(v.x, v.y);
    __half2 h23 = __floats2half2_rn(v.z, v.w);
    o[lane0 * 4 + reg]       = *(uint32_t*)&h01;
    o[(lane0 + 1) * 4 + reg] = *(uint32_t*)&h23;
}

__global__ __launch_bounds__(256) void conv_b_f16(const float* __restrict__ w0,
                                                  const float* __restrict__ w1,
                                                  const float* __restrict__ w2,
                                                  const float* __restrict__ w3,
                                                  uint32_t* __restrict__ out) {
    const int z = blockIdx.y;
    const float* w = (z == 0) ? w0 : (z == 1) ? w1 : (z == 2) ? w2 : w3;
    uint32_t* ob = out + (size_t)z * WSTRIDE;
    int i = (blockIdx.x * 256 + threadIdx.x) * 4;
    float4 v = *(const float4*)(w + i);
    int n = i >> 10, k = i & 1023;
    int nb = n >> 3, ni = n & 7, kb = k >> 4;
    int reg = (k & 15) >> 3;                         // same for all 4 ks
    int lane0 = ni * 4 + ((k & 7) >> 1);
    uint32_t* o = ob + ((size_t)(nb * 64 + kb) << 6);
    __half2 h01 = __floats2half2_rn(v.x, v.y);
    __half2 h23 = __floats2half2_rn(v.z, v.w);
    o[lane0 * 2 + reg]       = *(uint32_t*)&h01;
    o[(lane0 + 1) * 2 + reg] = *(uint32_t*)&h23;
}

// ---------------------------------------------------------------------------
// fp16 GEMM mainloop: 128x128 tile, BK=64 elems (4 k16-blocks), 16 stages,
// 3-stage bulk-copy ring. 4 warps (2m x 2n), warp tile 64x64 (mf=4, nf=8).
// Single fp16 pass: 8192 MMAs/tile (tf32 was 16384, bf16-3term 24576).
// ---------------------------------------------------------------------------
#define T32_STAGE 32768

__device__ __forceinline__ void f16_mainloop(const uint32_t* A0, const uint32_t* B0,
                                             uint32_t sb, int t, int lane,
                                             int warp_m, int warp_n,
                                             float acc[4][8][4]) {
    __shared__ __align__(8) unsigned long long mbars[3];
    const uint32_t mb = smem_u32(mbars);

    if (t == 0) {
        MBAR_INIT(mb + 0, 1);
        MBAR_INIT(mb + 8, 1);
        MBAR_INIT(mb + 16, 1);
    }
    __syncthreads();

    auto issue = [&](int s, int buf) {
        const uint32_t base = sb + buf * T32_STAGE;
        const uint32_t m = mb + buf * 8;
        const int kb0 = s * 4;                        // 4 k16-blocks per stage
        MBAR_EXPECT(m, 32768u);
#pragma unroll
        for (int rbl = 0; rbl < 8; rbl++)             // A: 8 runs x 2KB
            BULKCP(base + rbl * 2048, A0 + (((rbl << 6) + kb0) << 7), 2048u, m);
#pragma unroll
        for (int nbl = 0; nbl < 16; nbl++)            // B: 16 runs x 1KB
            BULKCP(base + 16384 + nbl * 1024, B0 + (((nbl << 6) + kb0) << 6), 1024u, m);
    };

    if (t == 0) { issue(0, 0); issue(1, 1); }

    for (int s = 0; s < 16; s++) {
        const int buf = s - (s / 3) * 3;              // s % 3
        const int par = (s / 3) & 1;
        MBAR_WAIT(mb + buf * 8, par);
        __syncthreads();                              // all warps done with buf (s+2)%3
        if (t == 0 && s + 2 < 16) issue(s + 2, (s + 2) % 3);

        const uint32_t sA = sb + buf * T32_STAGE;
        const uint32_t sB = sA + 16384;

#pragma unroll
        for (int ksp = 0; ksp < 2; ksp++) {
            const int ks0 = ksp * 2;
            uint32_t bf[2][8][2];
#pragma unroll
            for (int kk = 0; kk < 2; kk++)
#pragma unroll
                for (int nf = 0; nf < 8; nf++)
                    LDS64U(bf[kk][nf],
                           sB + ((((warp_n * 8 + nf) << 2) + ks0 + kk) << 8) + lane * 8);

            uint32_t ap[2][4];
            LDS128U(ap[0], sA + ((((warp_m * 4) << 2) + ks0) << 9) + lane * 16);
#pragma unroll
            for (int it = 0; it < 8; it++) {
                const int mf = it >> 1, kk = it & 1;
                if (it < 7) {
                    const int nmf = (it + 1) >> 1, nkk = (it + 1) & 1;
                    LDS128U(ap[(it + 1) & 1],
                            sA + ((((warp_m * 4 + nmf) << 2) + ks0 + nkk) << 9) + lane * 16);
                }
#pragma unroll
                for (int nf = 0; nf < 8; nf++)
                    MMAF16(acc[mf][nf], ap[it & 1], bf[kk][nf]);
            }
        }
    }
}

// QKV: split-bf16 epilogue (Q scaled by 0.125)
__global__ __launch_bounds__(128, 2)
void tgemm16(const uint32_t* __restrict__ At, const uint32_t* __restrict__ Wt,
             __nv_bfloat16* __restrict__ Ch0, __nv_bfloat16* __restrict__ Cl0,
             __nv_bfloat16* __restrict__ Ch1, __nv_bfloat16* __restrict__ Cl1,
             __nv_bfloat16* __restrict__ Ch2, __nv_bfloat16* __restrict__ Cl2) {
    const int t = threadIdx.x;
    const int lane = t & 31;
    const int wid = t >> 5;
    const int warp_m = wid >> 1, warp_n = wid & 1;
    const int z = blockIdx.z;
    const uint32_t sb = smem_u32(dynsm);

    // A: 8 rb-blocks per CTA row, each rb = 64 kb x 128 u32 = 8192 u32
    const uint32_t* A0 = At + ((size_t)blockIdx.y << 16);
    // B: 16 nb-blocks per CTA col, each nb = 64 kb x 64 u32 = 4096 u32
    const uint32_t* B0 = Wt + (size_t)z * WSTRIDE + ((size_t)blockIdx.x << 16);

    float acc[4][8][4];
#pragma unroll
    for (int i = 0; i < 4; i++)
#pragma unroll
        for (int j = 0; j < 8; j++)
#pragma unroll
            for (int r = 0; r < 4; r++) acc[i][j][r] = 0.f;

    f16_mainloop(A0, B0, sb, t, lane, warp_m, warp_n, acc);

    __nv_bfloat16* Ch = (z == 0) ? Ch0 : (z == 1) ? Ch1 : Ch2;
    __nv_bfloat16* Cl = (z == 0) ? Cl0 : (z == 1) ? Cl1 : Cl2;
    const float scale = (z == 0) ? 0.125f : 1.0f;
    const int bm = blockIdx.y << 7, bn = blockIdx.x << 7;
#pragma unroll
    for (int mf = 0; mf < 4; mf++) {
        const int r0 = bm + warp_m * 64 + mf * 16 + (lane >> 2);
#pragma unroll
        for (int nf = 0; nf < 8; nf++) {
            const int cn = bn + warp_n * 64 + nf * 8 + (lane & 3) * 2;
#pragma unroll
            for (int hh = 0; hh < 2; hh++) {
                float v0 = acc[mf][nf][hh * 2 + 0] * scale;
                float v1 = acc[mf][nf][hh * 2 + 1] * scale;
                uint32_t ph, pl;
                PSPLIT(ph, pl, v0, v1);
                size_t off = (size_t)(r0 + hh * 8) * DD + cn;
                *(uint32_t*)&Ch[off] = ph;
                *(uint32_t*)&Cl[off] = pl;
            }
        }
    }
}

// O projection: fp32 epilogue
__global__ __launch_bounds__(128, 2)
void tgemm16f(const uint32_t* __restrict__ At, const uint32_t* __restrict__ Wt,
              float* __restrict__ C) {
    const int t = threadIdx.x;
    const int lane = t & 31;
    const int wid = t >> 5;
    const int warp_m = wid >> 1, warp_n = wid & 1;
    const uint32_t sb = smem_u32(dynsm);

    const uint32_t* A0 = At + ((size_t)blockIdx.y << 16);
    const uint32_t* B0 = Wt + ((size_t)blockIdx.x << 16);

    float acc[4][8][4];
#pragma unroll
    for (int i = 0; i < 4; i++)
#pragma unroll
        for (int j = 0; j < 8; j++)
#pragma unroll
            for (int r = 0; r < 4; r++) acc[i][j][r] = 0.f;

    f16_mainloop(A0, B0, sb, t, lane, warp_m, warp_n, acc);

    const int bm = blockIdx.y << 7, bn = blockIdx.x << 7;
#pragma unroll
    for (int mf = 0; mf < 4; mf++) {
        const int r0 = bm + warp_m * 64 + mf * 16 + (lane >> 2);
#pragma unroll
        for (int nf = 0; nf < 8; nf++) {
            const int cn = bn + warp_n * 64 + nf * 8 + (lane & 3) * 2;
            *(float2*)&C[(size_t)r0 * DD + cn] =
                make_float2(acc[mf][nf][0], acc[mf][nf][1]);
            *(float2*)&C[(size_t)(r0 + 8) * DD + cn] =
                make_float2(acc[mf][nf][2], acc[mf][nf][3]);
        }
    }
}

// ---------------------------------------------------------------------------
// Tensor-core sliding-window flash attention; fp32 output. (unchanged)
// ---------------------------------------------------------------------------
#define APITCH 144
#define ATILE (64 * APITCH)
#define ABUF  (4 * ATILE)

__global__ __launch_bounds__(256, 1)
void swa_mma(const __nv_bfloat16* __restrict__ Qh, const __nv_bfloat16* __restrict__ Ql,
             const __nv_bfloat16* __restrict__ Kh, const __nv_bfloat16* __restrict__ Kl,
             const __nv_bfloat16* __restrict__ Vh, const __nv_bfloat16* __restrict__ Vl,
             float* __restrict__ O) {
    const int jq = blockIdx.x, h = blockIdx.y, b = blockIdx.z;
    const int t = threadIdx.x, lane = t & 31, wid = t >> 5;
    const int tq = wid * 16;
    const uint32_t sb = smem_u32(dynsm);
    const int kv0 = 128 * jq - 256;

    uint32_t qA[2][4][4];
    {
        const int r0 = 128 * jq + tq + (lane >> 2);
        const size_t rowb = (size_t)(b * SS + r0) * DD + h * DH + 2 * (lane & 3);
        const __nv_bfloat16* Qs[2] = {Qh, Ql};
#pragma unroll
        for (int term = 0; term < 2; term++)
#pragma unroll
            for (int kf = 0; kf < 4; kf++) {
                qA[term][kf][0] = *(const uint32_t*)(Qs[term] + rowb + kf * 16);
                qA[term][kf][1] = *(const uint32_t*)(Qs[term] + rowb + 8 * DD + kf * 16);
                qA[term][kf][2] = *(const uint32_t*)(Qs[term] + rowb + kf * 16 + 8);
                qA[term][kf][3] = *(const uint32_t*)(Qs[term] + rowb + 8 * DD + kf * 16 + 8);
            }
    }

    const __nv_bfloat16* srcs[4] = {Kh, Kl, Vh, Vl};
    auto load_chunk = [&](int c, int buf) {
        const int kbase = kv0 + 64 * c;
#pragma unroll
        for (int it = 0; it < 8; it++) {
            int idx = t + it * 256;
            int tensor = idx >> 9;
            int row = (idx >> 3) & 63;
            int dch = idx & 7;
            int kp = kbase + row;
            int ok = (kp >= 0) ? 16 : 0;
            int kpc = kp >= 0 ? kp : 0;
            uint32_t dst = sb + buf * ABUF + tensor * ATILE + row * APITCH + dch * 16;
            const void* src = srcs[tensor] + (size_t)(b * SS + kpc) * DD + h * DH + dch * 8;
            CPASYNC16Z(dst, src, ok);
        }
    };

    float o[8][4];
#pragma unroll
    for (int nf = 0; nf < 8; nf++)
#pragma unroll
        for (int r = 0; r < 4; r++) o[nf][r] = 0.f;
    float m0 = -1e30f, m1 = -1e30f, lp0 = 0.f, lp1 = 0.f;

    const int cmin = (tq + 1) >> 6;
    const int cmax = (tq + 271) >> 6;

    load_chunk(0, 0);
    CPCOMMIT();

    for (int c = 0; c < 6; c++) {
        if (c < 5) {
            load_chunk(c + 1, (c + 1) & 1);
            CPCOMMIT();
            CPWAIT1();
        } else {
            CPWAIT0();
        }
        __syncthreads();

        const int kbase = kv0 + 64 * c;
        if (c >= cmin && c <= cmax && kbase + 63 >= 0) {
            const uint32_t kvb = sb + (c & 1) * ABUF;

            float s[8][4];
#pragma unroll
            for (int nf = 0; nf < 8; nf++)
#pragma unroll
                for (int r = 0; r < 4; r++) s[nf][r] = 0.f;

#pragma unroll
            for (int kf = 0; kf < 4; kf++) {
#pragma unroll
                for (int kg = 0; kg < 4; kg++) {
                    uint32_t addr = kvb +
                        (kg * 16 + (lane & 7) + ((lane >> 4) << 3)) * APITCH +
                        ((lane >> 3) & 1) * 16 + kf * 32;
                    uint32_t bh[4], bl[4];
                    LDSM4(bh[0], bh[1], bh[2], bh[3], addr);
                    LDSM4(bl[0], bl[1], bl[2], bl[3], addr + ATILE);
                    MMA16816(s[2 * kg],     qA[0][kf], &bh[0]);
                    MMA16816(s[2 * kg],     qA[0][kf], &bl[0]);
                    MMA16816(s[2 * kg],     qA[1][kf], &bh[0]);
                    MMA16816(s[2 * kg + 1], qA[0][kf], &bh[2]);
                    MMA16816(s[2 * kg + 1], qA[0][kf], &bl[2]);
                    MMA16816(s[2 * kg + 1], qA[1][kf], &bh[2]);
                }
            }

            {
                const int qg = 128 * jq + tq + (lane >> 2);
                const int d0 = qg - (kbase + 2 * (lane & 3));
#pragma unroll
                for (int nf = 0; nf < 8; nf++) {
                    int e = d0 - nf * 8;
                    s[nf][0] = ((unsigned)e <= 255u)       ? s[nf][0] : -1e30f;
                    s[nf][1] = ((unsigned)(e - 1) <= 255u) ? s[nf][1] : -1e30f;
                    s[nf][2] = ((unsigned)(e + 8) <= 255u) ? s[nf][2] : -1e30f;
                    s[nf][3] = ((unsigned)(e + 7) <= 255u) ? s[nf][3] : -1e30f;
                }
            }

            float mx0 = -1e30f, mx1 = -1e30f;
#pragma unroll
            for (int nf = 0; nf < 8; nf++) {
                mx0 = fmaxf(mx0, fmaxf(s[nf][0], s[nf][1]));
                mx1 = fmaxf(mx1, fmaxf(s[nf][2], s[nf][3]));
            }
            mx0 = fmaxf(mx0, __shfl_xor_sync(0xffffffffu, mx0, 1));
            mx0 = fmaxf(mx0, __shfl_xor_sync(0xffffffffu, mx0, 2));
            mx1 = fmaxf(mx1, __shfl_xor_sync(0xffffffffu, mx1, 1));
            mx1 = fmaxf(mx1, __shfl_xor_sync(0xffffffffu, mx1, 2));

            float mn0 = fmaxf(m0, mx0), mn1 = fmaxf(m1, mx1);
            float c0 = __expf(m0 - mn0), c1 = __expf(m1 - mn1);
            m0 = mn0; m1 = mn1;

            float ls0 = 0.f, ls1 = 0.f;
#pragma unroll
            for (int nf = 0; nf < 8; nf++) {
                s[nf][0] = __expf(s[nf][0] - mn0);
                s[nf][1] = __expf(s[nf][1] - mn0);
                s[nf][2] = __expf(s[nf][2] - mn1);
                s[nf][3] = __expf(s[nf][3] - mn1);
                ls0 += s[nf][0] + s[nf][1];
                ls1 += s[nf][2] + s[nf][3];
            }
            lp0 = lp0 * c0 + ls0;
            lp1 = lp1 * c1 + ls1;
#pragma unroll
            for (int nf = 0; nf < 8; nf++) {
                o[nf][0] *= c0; o[nf][1] *= c0;
                o[nf][2] *= c1; o[nf][3] *= c1;
            }

#pragma unroll
            for (int kf = 0; kf < 4; kf++) {
                uint32_t pha[4], pla[4];
                PSPLIT(pha[0], pla[0], s[2 * kf][0], s[2 * kf][1]);
                PSPLIT(pha[1], pla[1], s[2 * kf][2], s[2 * kf][3]);
                PSPLIT(pha[2], pla[2], s[2 * kf + 1][0], s[2 * kf + 1][1]);
                PSPLIT(pha[3], pla[3], s[2 * kf + 1][2], s[2 * kf + 1][3]);
#pragma unroll
                for (int dg = 0; dg < 4; dg++) {
                    uint32_t vaddr = kvb + 2 * ATILE +
                        (kf * 16 + (lane & 15)) * APITCH + dg * 32 +
                        ((lane >> 4) & 1) * 16;
                    uint32_t vh4[4], vl4[4];
                    LDSM4T(vh4[0], vh4[1], vh4[2], vh4[3], vaddr);
                    LDSM4T(vl4[0], vl4[1], vl4[2], vl4[3], vaddr + ATILE);
                    MMA16816(o[2 * dg],     pha, &vh4[0]);
                    MMA16816(o[2 * dg],     pha, &vl4[0]);
                    MMA16816(o[2 * dg],     pla, &vh4[0]);
                    MMA16816(o[2 * dg + 1], pha, &vh4[2]);
                    MMA16816(o[2 * dg + 1], pha, &vl4[2]);
                    MMA16816(o[2 * dg + 1], pla, &vh4[2]);
                }
            }
        }
        __syncthreads();
    }

    lp0 += __shfl_xor_sync(0xffffffffu, lp0, 1);
    lp0 += __shfl_xor_sync(0xffffffffu, lp0, 2);
    lp1 += __shfl_xor_sync(0xffffffffu, lp1, 1);
    lp1 += __shfl_xor_sync(0xffffffffu, lp1, 2);
    const float inv0 = 1.f / lp0, inv1 = 1.f / lp1;

    const int r0 = 128 * jq + tq + (lane >> 2);
    const size_t ob = (size_t)(b * SS + r0) * DD + h * DH + 2 * (lane & 3);
#pragma unroll
    for (int nf = 0; nf < 8; nf++) {
        *(float2*)&O[ob + nf * 8] = make_float2(o[nf][0] * inv0, o[nf][1] * inv0);
        *(float2*)&O[ob + 8 * DD + nf * 8] = make_float2(o[nf][2] * inv1, o[nf][3] * inv1);
    }
}

// ---------------------------------------------------------------------------
extern "C" void kernel_launch(void* const* d_in, const int* in_sizes, int n_in,
                              void* d_out, int out_size) {
    const float* x = (const float*)d_in[0];
    const float* w[4] = {(const float*)d_in[1], (const float*)d_in[2],
                         (const float*)d_in[3], (const float*)d_in[4]};
    float* out = (float*)d_out;

    uint32_t *xt, *wt;
    float* ao;
    __nv_bfloat16 *qh, *ql, *kh, *kl, *vh, *vl;
    cudaGetSymbolAddress((void**)&xt, g_xt);
    cudaGetSymbolAddress((void**)&wt, g_wt);
    cudaGetSymbolAddress((void**)&ao, g_ao);
    cudaGetSymbolAddress((void**)&qh, g_qh);
    cudaGetSymbolAddress((void**)&ql, g_ql);
    cudaGetSymbolAddress((void**)&kh, g_kh);
    cudaGetSymbolAddress((void**)&kl, g_kl);
    cudaGetSymbolAddress((void**)&vh, g_vh);
    cudaGetSymbolAddress((void**)&vl, g_vl);

    const int DYNSM_T = 3 * T32_STAGE;    // 98304
    const int DYNSM_A = 2 * ABUF;         // 73728
    cudaFuncSetAttribute(tgemm16,  cudaFuncAttributeMaxDynamicSharedMemorySize, DYNSM_T);
    cudaFuncSetAttribute(tgemm16f, cudaFuncAttributeMaxDynamicSharedMemorySize, DYNSM_T);
    cudaFuncSetAttribute(swa_mma,  cudaFuncAttributeMaxDynamicSharedMemorySize, DYNSM_A);

    conv_a_f16<<<(MM * DD) / 1024, 256>>>(x, xt);
    conv_b_f16<<<dim3((DD * DD) / 1024, 4), 256>>>(w[0], w[1], w[2], w[3], wt);

    dim3 gq(DD / 128, MM / 128, 3);   // (8, 64, 3)
    tgemm16<<<gq, 128, DYNSM_T>>>(xt, wt, qh, ql, kh, kl, vh, vl);

    dim3 ga(SS / 128, HH, BB);        // (32, 16, 2)
    swa_mma<<<ga, 256, DYNSM_A>>>(qh, ql, kh, kl, vh, vl, ao);

    // reuse xt for ao in fp16 fragment-major (x is dead after QKV GEMM)
    conv_a_f16<<<(MM * DD) / 1024, 256>>>(ao, xt);

    dim3 go(DD / 128, MM / 128);      // (8, 64)
    tgemm16f<<<go, 128, DYNSM_T>>>(xt, wt + 3 * (size_t)WSTRIDE, out);
}

// round 11
// speedup vs baseline: 1.9916x; 1.2770x over previous
#include <cuda_runtime.h>
#include <cuda_bf16.h>
#include <cuda_fp16.h>
#include <math.h>
#include <stdint.h>

#define BB 2
#define SS 4096
#define DD 1024
#define HH 16
#define DH 64
#define WW 256
#define MM (BB * SS)

// ---------------- device scratch (allocation-free rule) ----------------
__device__ uint32_t g_xt[MM * DD / 2];      // x (then ao) in fp16, A-fragment-major
__device__ uint32_t g_wt[2 * DD * DD];      // wq,wk,wv,wo in fp16, B-fragment-major
__device__ float g_ao[MM * DD];             // attention output, fp32
__device__ __half g_q16[MM * DD];           // Q (pre-scaled), fp16 row-major
__device__ __half g_k16[MM * DD];
__device__ __half g_v16[MM * DD];

#define WSTRIDE (DD * DD / 2)

// ---------------- family-portable PTX helpers ----------------
__device__ __forceinline__ uint32_t smem_u32(const void* p) {
    uint32_t a;
    asm("{ .reg .u64 t; cvta.to.shared.u64 t, %1; cvt.u32.u64 %0, t; }"
        : "=r"(a) : "l"(p));
    return a;
}

#define LDSM4(r0, r1, r2, r3, addr)                                              \
    asm volatile("ldmatrix.sync.aligned.m8n8.x4.shared.b16 {%0,%1,%2,%3}, [%4];"  \
                 : "=r"(r0), "=r"(r1), "=r"(r2), "=r"(r3) : "r"(addr))
#define LDSM4T(r0, r1, r2, r3, addr)                                             \
    asm volatile("ldmatrix.sync.aligned.m8n8.x4.trans.shared.b16 {%0,%1,%2,%3}, [%4];" \
                 : "=r"(r0), "=r"(r1), "=r"(r2), "=r"(r3) : "r"(addr))
#define LDS128U(r, addr)                                                         \
    asm volatile("ld.shared.v4.b32 {%0,%1,%2,%3}, [%4];"                          \
                 : "=r"((r)[0]), "=r"((r)[1]), "=r"((r)[2]), "=r"((r)[3])         \
                 : "r"(addr))
#define LDS64U(r, addr)                                                          \
    asm volatile("ld.shared.v2.b32 {%0,%1}, [%2];"                                \
                 : "=r"((r)[0]), "=r"((r)[1]) : "r"(addr))

#define MMAF16(d, a, b)                                                          \
    asm volatile(                                                                \
        "mma.sync.aligned.m16n8k16.row.col.f32.f16.f16.f32 "                     \
        "{%0,%1,%2,%3},{%4,%5,%6,%7},{%8,%9},{%0,%1,%2,%3};"                     \
        : "+f"((d)[0]), "+f"((d)[1]), "+f"((d)[2]), "+f"((d)[3])                 \
        : "r"((a)[0]), "r"((a)[1]), "r"((a)[2]), "r"((a)[3]),                    \
          "r"((b)[0]), "r"((b)[1]))

#define CPASYNC16Z(dst, src, sz)                                                 \
    asm volatile("cp.async.cg.shared.global [%0], [%1], 16, %2;"                  \
                 :: "r"(dst), "l"(src), "r"(sz))
#define CPCOMMIT() asm volatile("cp.async.commit_group;" ::: "memory")
#define CPWAIT0()  asm volatile("cp.async.wait_group 0;" ::: "memory")
#define CPWAIT1()  asm volatile("cp.async.wait_group 1;" ::: "memory")

// --- bulk async copy + mbarrier (sm_90 baseline, family-portable) ---
#define MBAR_INIT(a, c)                                                          \
    asm volatile("mbarrier.init.shared.b64 [%0], %1;" :: "r"(a), "r"(c) : "memory")
#define MBAR_EXPECT(a, bytes)                                                    \
    asm volatile("mbarrier.arrive.expect_tx.shared.b64 _, [%0], %1;"              \
                 :: "r"(a), "r"(bytes) : "memory")
#define BULKCP(dst, src, sz, mb)                                                 \
    asm volatile("cp.async.bulk.shared::cta.global.mbarrier::complete_tx::bytes " \
                 "[%0], [%1], %2, [%3];"                                          \
                 :: "r"(dst), "l"(src), "r"(sz), "r"(mb) : "memory")
#define MBAR_WAIT(a, p)                                                          \
    asm volatile(                                                                \
        "{\n\t.reg .pred P;\n\t"                                                 \
        "W_%=:\n\t"                                                              \
        "mbarrier.try_wait.parity.acquire.cta.shared::cta.b64 P, [%0], %1;\n\t"  \
        "@P bra.uni D_%=;\n\t"                                                   \
        "bra.uni W_%=;\n\t"                                                      \
        "D_%=:\n\t}"                                                             \
        :: "r"(a), "r"(p) : "memory")

extern __shared__ char dynsm[];

// ---------------------------------------------------------------------------
// Converters to fp16 fragment-major layouts (m16n8k16).
// ---------------------------------------------------------------------------
__global__ __launch_bounds__(256) void conv_a_f16(const float* __restrict__ x,
                                                  uint32_t* __restrict__ out) {
    int i = (blockIdx.x * 256 + threadIdx.x) * 4;
    float4 v = *(const float4*)(x + i);
    int r = i >> 10, c = i & 1023;
    int rb = r >> 4, ri = r & 15, kb = c >> 4;
    int reg = (ri >> 3) + 2 * ((c & 15) >> 3);
    int lane0 = (ri & 7) * 4 + ((c & 7) >> 1);
    uint32_t* o = out + ((size_t)(rb * 64 + kb) << 7);
    __half2 h01 = __floats2half2_rn(v.x, v.y);
    __half2 h23 = __floats2half2_rn(v.z, v.w);
    o[lane0 * 4 + reg]       = *(uint32_t*)&h01;
    o[(lane0 + 1) * 4 + reg] = *(uint32_t*)&h23;
}

__global__ __launch_bounds__(256) void conv_b_f16(const float* __restrict__ w0,
                                                  const float* __restrict__ w1,
                                                  const float* __restrict__ w2,
                                                  const float* __restrict__ w3,
                                                  uint32_t* __restrict__ out) {
    const int z = blockIdx.y;
    const float* w = (z == 0) ? w0 : (z == 1) ? w1 : (z == 2) ? w2 : w3;
    uint32_t* ob = out + (size_t)z * WSTRIDE;
    int i = (blockIdx.x * 256 + threadIdx.x) * 4;
    float4 v = *(const float4*)(w + i);
    int n = i >> 10, k = i & 1023;
    int nb = n >> 3, ni = n & 7, kb = k >> 4;
    int reg = (k & 15) >> 3;
    int lane0 = ni * 4 + ((k & 7) >> 1);
    uint32_t* o = ob + ((size_t)(nb * 64 + kb) << 6);
    __half2 h01 = __floats2half2_rn(v.x, v.y);
    __half2 h23 = __floats2half2_rn(v.z, v.w);
    o[lane0 * 2 + reg]       = *(uint32_t*)&h01;
    o[(lane0 + 1) * 2 + reg] = *(uint32_t*)&h23;
}

// ---------------------------------------------------------------------------
// fp16 GEMM mainloop: 128x128 tile, BK=64, 16 stages, 3-stage bulk-copy ring.
// 4 warps (2m x 2n), warp tile 64x64.
// ---------------------------------------------------------------------------
#define T32_STAGE 32768

__device__ __forceinline__ void f16_mainloop(const uint32_t* A0, const uint32_t* B0,
                                             uint32_t sb, int t, int lane,
                                             int warp_m, int warp_n,
                                             float acc[4][8][4]) {
    __shared__ __align__(8) unsigned long long mbars[3];
    const uint32_t mb = smem_u32(mbars);

    if (t == 0) {
        MBAR_INIT(mb + 0, 1);
        MBAR_INIT(mb + 8, 1);
        MBAR_INIT(mb + 16, 1);
    }
    __syncthreads();

    auto issue = [&](int s, int buf) {
        const uint32_t base = sb + buf * T32_STAGE;
        const uint32_t m = mb + buf * 8;
        const int kb0 = s * 4;
        MBAR_EXPECT(m, 32768u);
#pragma unroll
        for (int rbl = 0; rbl < 8; rbl++)
            BULKCP(base + rbl * 2048, A0 + (((rbl << 6) + kb0) << 7), 2048u, m);
#pragma unroll
        for (int nbl = 0; nbl < 16; nbl++)
            BULKCP(base + 16384 + nbl * 1024, B0 + (((nbl << 6) + kb0) << 6), 1024u, m);
    };

    if (t == 0) { issue(0, 0); issue(1, 1); }

    for (int s = 0; s < 16; s++) {
        const int buf = s - (s / 3) * 3;
        const int par = (s / 3) & 1;
        MBAR_WAIT(mb + buf * 8, par);
        __syncthreads();
        if (t == 0 && s + 2 < 16) issue(s + 2, (s + 2) % 3);

        const uint32_t sA = sb + buf * T32_STAGE;
        const uint32_t sB = sA + 16384;

#pragma unroll
        for (int ksp = 0; ksp < 2; ksp++) {
            const int ks0 = ksp * 2;
            uint32_t bf[2][8][2];
#pragma unroll
            for (int kk = 0; kk < 2; kk++)
#pragma unroll
                for (int nf = 0; nf < 8; nf++)
                    LDS64U(bf[kk][nf],
                           sB + ((((warp_n * 8 + nf) << 2) + ks0 + kk) << 8) + lane * 8);

            uint32_t ap[2][4];
            LDS128U(ap[0], sA + ((((warp_m * 4) << 2) + ks0) << 9) + lane * 16);
#pragma unroll
            for (int it = 0; it < 8; it++) {
                const int mf = it >> 1, kk = it & 1;
                if (it < 7) {
                    const int nmf = (it + 1) >> 1, nkk = (it + 1) & 1;
                    LDS128U(ap[(it + 1) & 1],
                            sA + ((((warp_m * 4 + nmf) << 2) + ks0 + nkk) << 9) + lane * 16);
                }
#pragma unroll
                for (int nf = 0; nf < 8; nf++)
                    MMAF16(acc[mf][nf], ap[it & 1], bf[kk][nf]);
            }
        }
    }
}

// QKV: plain-fp16 epilogue (Q scaled by 0.125)
__global__ __launch_bounds__(128, 2)
void tgemm16(const uint32_t* __restrict__ At, const uint32_t* __restrict__ Wt,
             __half* __restrict__ Q16, __half* __restrict__ K16,
             __half* __restrict__ V16) {
    const int t = threadIdx.x;
    const int lane = t & 31;
    const int wid = t >> 5;
    const int warp_m = wid >> 1, warp_n = wid & 1;
    const int z = blockIdx.z;
    const uint32_t sb = smem_u32(dynsm);

    const uint32_t* A0 = At + ((size_t)blockIdx.y << 16);
    const uint32_t* B0 = Wt + (size_t)z * WSTRIDE + ((size_t)blockIdx.x << 16);

    float acc[4][8][4];
#pragma unroll
    for (int i = 0; i < 4; i++)
#pragma unroll
        for (int j = 0; j < 8; j++)
#pragma unroll
            for (int r = 0; r < 4; r++) acc[i][j][r] = 0.f;

    f16_mainloop(A0, B0, sb, t, lane, warp_m, warp_n, acc);

    __half* Cd = (z == 0) ? Q16 : (z == 1) ? K16 : V16;
    const float scale = (z == 0) ? 0.125f : 1.0f;
    const int bm = blockIdx.y << 7, bn = blockIdx.x << 7;
#pragma unroll
    for (int mf = 0; mf < 4; mf++) {
        const int r0 = bm + warp_m * 64 + mf * 16 + (lane >> 2);
#pragma unroll
        for (int nf = 0; nf < 8; nf++) {
            const int cn = bn + warp_n * 64 + nf * 8 + (lane & 3) * 2;
#pragma unroll
            for (int hh = 0; hh < 2; hh++) {
                __half2 hv = __floats2half2_rn(acc[mf][nf][hh * 2 + 0] * scale,
                                               acc[mf][nf][hh * 2 + 1] * scale);
                *(uint32_t*)&Cd[(size_t)(r0 + hh * 8) * DD + cn] = *(uint32_t*)&hv;
            }
        }
    }
}

// O projection: fp32 epilogue
__global__ __launch_bounds__(128, 2)
void tgemm16f(const uint32_t* __restrict__ At, const uint32_t* __restrict__ Wt,
              float* __restrict__ C) {
    const int t = threadIdx.x;
    const int lane = t & 31;
    const int wid = t >> 5;
    const int warp_m = wid >> 1, warp_n = wid & 1;
    const uint32_t sb = smem_u32(dynsm);

    const uint32_t* A0 = At + ((size_t)blockIdx.y << 16);
    const uint32_t* B0 = Wt + ((size_t)blockIdx.x << 16);

    float acc[4][8][4];
#pragma unroll
    for (int i = 0; i < 4; i++)
#pragma unroll
        for (int j = 0; j < 8; j++)
#pragma unroll
            for (int r = 0; r < 4; r++) acc[i][j][r] = 0.f;

    f16_mainloop(A0, B0, sb, t, lane, warp_m, warp_n, acc);

    const int bm = blockIdx.y << 7, bn = blockIdx.x << 7;
#pragma unroll
    for (int mf = 0; mf < 4; mf++) {
        const int r0 = bm + warp_m * 64 + mf * 16 + (lane >> 2);
#pragma unroll
        for (int nf = 0; nf < 8; nf++) {
            const int cn = bn + warp_n * 64 + nf * 8 + (lane & 3) * 2;
            *(float2*)&C[(size_t)r0 * DD + cn] =
                make_float2(acc[mf][nf][0], acc[mf][nf][1]);
            *(float2*)&C[(size_t)(r0 + 8) * DD + cn] =
                make_float2(acc[mf][nf][2], acc[mf][nf][3]);
        }
    }
}

// ---------------------------------------------------------------------------
// fp16 single-pass sliding-window flash attention; fp32 output.
// Grid (S/128, H, B); 256 thr = 8 warps x 16 q-rows. K/V chunks of 64 keys,
// double-buffered cp.async; 2 MMAs per (kf, frag-pair) step.
// ---------------------------------------------------------------------------
#define APITCH 144
#define ATILE (64 * APITCH)    // 9216
#define ABUF  (2 * ATILE)      // K, V

__global__ __launch_bounds__(256, 2)
void swa_mma(const __half* __restrict__ Q16, const __half* __restrict__ K16,
             const __half* __restrict__ V16, float* __restrict__ O) {
    const int jq = blockIdx.x, h = blockIdx.y, b = blockIdx.z;
    const int t = threadIdx.x, lane = t & 31, wid = t >> 5;
    const int tq = wid * 16;
    const uint32_t sb = smem_u32(dynsm);
    const int kv0 = 128 * jq - 256;

    // Q fragments (fp16, pre-scaled): Dh=64 -> 4 k16-blocks
    uint32_t qA[4][4];
    {
        const int r0 = 128 * jq + tq + (lane >> 2);
        const size_t rowb = (size_t)(b * SS + r0) * DD + h * DH + 2 * (lane & 3);
#pragma unroll
        for (int kf = 0; kf < 4; kf++) {
            qA[kf][0] = *(const uint32_t*)(Q16 + rowb + kf * 16);
            qA[kf][1] = *(const uint32_t*)(Q16 + rowb + 8 * DD + kf * 16);
            qA[kf][2] = *(const uint32_t*)(Q16 + rowb + kf * 16 + 8);
            qA[kf][3] = *(const uint32_t*)(Q16 + rowb + 8 * DD + kf * 16 + 8);
        }
    }

    const __half* srcs[2] = {K16, V16};
    auto load_chunk = [&](int c, int buf) {
        const int kbase = kv0 + 64 * c;
#pragma unroll
        for (int it = 0; it < 4; it++) {
            int idx = t + it * 256;            // 0..1023
            int tensor = idx >> 9;             // 0..1
            int row = (idx >> 3) & 63;
            int dch = idx & 7;
            int kp = kbase + row;
            int ok = (kp >= 0) ? 16 : 0;
            int kpc = kp >= 0 ? kp : 0;
            uint32_t dst = sb + buf * ABUF + tensor * ATILE + row * APITCH + dch * 16;
            const void* src = srcs[tensor] + (size_t)(b * SS + kpc) * DD + h * DH + dch * 8;
            CPASYNC16Z(dst, src, ok);
        }
    };

    float o[8][4];
#pragma unroll
    for (int nf = 0; nf < 8; nf++)
#pragma unroll
        for (int r = 0; r < 4; r++) o[nf][r] = 0.f;
    float m0 = -1e30f, m1 = -1e30f, lp0 = 0.f, lp1 = 0.f;

    const int cmin = (tq + 1) >> 6;
    const int cmax = (tq + 271) >> 6;

    load_chunk(0, 0);
    CPCOMMIT();

    for (int c = 0; c < 6; c++) {
        if (c < 5) {
            load_chunk(c + 1, (c + 1) & 1);
            CPCOMMIT();
            CPWAIT1();
        } else {
            CPWAIT0();
        }
        __syncthreads();

        const int kbase = kv0 + 64 * c;
        if (c >= cmin && c <= cmax && kbase + 63 >= 0) {
            const uint32_t kvb = sb + (c & 1) * ABUF;

            // ---- S = Q K^T (single fp16 pass) ----
            float s[8][4];
#pragma unroll
            for (int nf = 0; nf < 8; nf++)
#pragma unroll
                for (int r = 0; r < 4; r++) s[nf][r] = 0.f;

#pragma unroll
            for (int kf = 0; kf < 4; kf++) {
#pragma unroll
                for (int kg = 0; kg < 4; kg++) {
                    uint32_t addr = kvb +
                        (kg * 16 + (lane & 7) + ((lane >> 4) << 3)) * APITCH +
                        ((lane >> 3) & 1) * 16 + kf * 32;
                    uint32_t bh[4];
                    LDSM4(bh[0], bh[1], bh[2], bh[3], addr);
                    MMAF16(s[2 * kg],     qA[kf], &bh[0]);
                    MMAF16(s[2 * kg + 1], qA[kf], &bh[2]);
                }
            }

            // ---- band mask: valid iff 0 <= q - key <= 255 ----
            {
                const int qg = 128 * jq + tq + (lane >> 2);
                const int d0 = qg - (kbase + 2 * (lane & 3));
#pragma unroll
                for (int nf = 0; nf < 8; nf++) {
                    int e = d0 - nf * 8;
                    s[nf][0] = ((unsigned)e <= 255u)       ? s[nf][0] : -1e30f;
                    s[nf][1] = ((unsigned)(e - 1) <= 255u) ? s[nf][1] : -1e30f;
                    s[nf][2] = ((unsigned)(e + 8) <= 255u) ? s[nf][2] : -1e30f;
                    s[nf][3] = ((unsigned)(e + 7) <= 255u) ? s[nf][3] : -1e30f;
                }
            }

            // ---- online softmax ----
            float mx0 = -1e30f, mx1 = -1e30f;
#pragma unroll
            for (int nf = 0; nf < 8; nf++) {
                mx0 = fmaxf(mx0, fmaxf(s[nf][0], s[nf][1]));
                mx1 = fmaxf(mx1, fmaxf(s[nf][2], s[nf][3]));
            }
            mx0 = fmaxf(mx0, __shfl_xor_sync(0xffffffffu, mx0, 1));
            mx0 = fmaxf(mx0, __shfl_xor_sync(0xffffffffu, mx0, 2));
            mx1 = fmaxf(mx1, __shfl_xor_sync(0xffffffffu, mx1, 1));
            mx1 = fmaxf(mx1, __shfl_xor_sync(0xffffffffu, mx1, 2));

            float mn0 = fmaxf(m0, mx0), mn1 = fmaxf(m1, mx1);
            float c0 = __expf(m0 - mn0), c1 = __expf(m1 - mn1);
            m0 = mn0; m1 = mn1;

            float ls0 = 0.f, ls1 = 0.f;
#pragma unroll
            for (int nf = 0; nf < 8; nf++) {
                s[nf][0] = __expf(s[nf][0] - mn0);
                s[nf][1] = __expf(s[nf][1] - mn0);
                s[nf][2] = __expf(s[nf][2] - mn1);
                s[nf][3] = __expf(s[nf][3] - mn1);
                ls0 += s[nf][0] + s[nf][1];
                ls1 += s[nf][2] + s[nf][3];
            }
            lp0 = lp0 * c0 + ls0;
            lp1 = lp1 * c1 + ls1;
#pragma unroll
            for (int nf = 0; nf < 8; nf++) {
                o[nf][0] *= c0; o[nf][1] *= c0;
                o[nf][2] *= c1; o[nf][3] *= c1;
            }

            // ---- O += P V (single fp16 pass) ----
#pragma unroll
            for (int kf = 0; kf < 4; kf++) {
                uint32_t pa[4];
                __half2 p0 = __floats2half2_rn(s[2 * kf][0], s[2 * kf][1]);
                __half2 p1 = __floats2half2_rn(s[2 * kf][2], s[2 * kf][3]);
                __half2 p2 = __floats2half2_rn(s[2 * kf + 1][0], s[2 * kf + 1][1]);
                __half2 p3 = __floats2half2_rn(s[2 * kf + 1][2], s[2 * kf + 1][3]);
                pa[0] = *(uint32_t*)&p0;
                pa[1] = *(uint32_t*)&p1;
                pa[2] = *(uint32_t*)&p2;
                pa[3] = *(uint32_t*)&p3;
#pragma unroll
                for (int dg = 0; dg < 4; dg++) {
                    uint32_t vaddr = kvb + ATILE +
                        (kf * 16 + (lane & 15)) * APITCH + dg * 32 +
                        ((lane >> 4) & 1) * 16;
                    uint32_t vh4[4];
                    LDSM4T(vh4[0], vh4[1], vh4[2], vh4[3], vaddr);
                    MMAF16(o[2 * dg],     pa, &vh4[0]);
                    MMAF16(o[2 * dg + 1], pa, &vh4[2]);
                }
            }
        }
        __syncthreads();
    }

    lp0 += __shfl_xor_sync(0xffffffffu, lp0, 1);
    lp0 += __shfl_xor_sync(0xffffffffu, lp0, 2);
    lp1 += __shfl_xor_sync(0xffffffffu, lp1, 1);
    lp1 += __shfl_xor_sync(0xffffffffu, lp1, 2);
    const float inv0 = 1.f / lp0, inv1 = 1.f / lp1;

    const int r0 = 128 * jq + tq + (lane >> 2);
    const size_t ob = (size_t)(b * SS + r0) * DD + h * DH + 2 * (lane & 3);
#pragma unroll
    for (int nf = 0; nf < 8; nf++) {
        *(float2*)&O[ob + nf * 8] = make_float2(o[nf][0] * inv0, o[nf][1] * inv0);
        *(float2*)&O[ob + 8 * DD + nf * 8] = make_float2(o[nf][2] * inv1, o[nf][3] * inv1);
    }
}

// ---------------------------------------------------------------------------
extern "C" void kernel_launch(void* const* d_in, const int* in_sizes, int n_in,
                              void* d_out, int out_size) {
    const float* x = (const float*)d_in[0];
    const float* w[4] = {(const float*)d_in[1], (const float*)d_in[2],
                         (const float*)d_in[3], (const float*)d_in[4]};
    float* out = (float*)d_out;

    uint32_t *xt, *wt;
    float* ao;
    __half *q16, *k16, *v16;
    cudaGetSymbolAddress((void**)&xt,  g_xt);
    cudaGetSymbolAddress((void**)&wt,  g_wt);
    cudaGetSymbolAddress((void**)&ao,  g_ao);
    cudaGetSymbolAddress((void**)&q16, g_q16);
    cudaGetSymbolAddress((void**)&k16, g_k16);
    cudaGetSymbolAddress((void**)&v16, g_v16);

    const int DYNSM_T = 3 * T32_STAGE;    // 98304
    const int DYNSM_A = 2 * ABUF;         // 36864
    cudaFuncSetAttribute(tgemm16,  cudaFuncAttributeMaxDynamicSharedMemorySize, DYNSM_T);
    cudaFuncSetAttribute(tgemm16f, cudaFuncAttributeMaxDynamicSharedMemorySize, DYNSM_T);
    cudaFuncSetAttribute(swa_mma,  cudaFuncAttributeMaxDynamicSharedMemorySize, DYNSM_A);

    conv_a_f16<<<(MM * DD) / 1024, 256>>>(x, xt);
    conv_b_f16<<<dim3((DD * DD) / 1024, 4), 256>>>(w[0], w[1], w[2], w[3], wt);

    dim3 gq(DD / 128, MM / 128, 3);   // (8, 64, 3)
    tgemm16<<<gq, 128, DYNSM_T>>>(xt, wt, q16, k16, v16);

    dim3 ga(SS / 128, HH, BB);        // (32, 16, 2)
    swa_mma<<<ga, 256, DYNSM_A>>>(q16, k16, v16, ao);

    // reuse xt for ao in fp16 fragment-major (x is dead after QKV GEMM)
    conv_a_f16<<<(MM * DD) / 1024, 256>>>(ao, xt);

    dim3 go(DD / 128, MM / 128);      // (8, 64)
    tgemm16f<<<go, 128, DYNSM_T>>>(xt, wt + 3 * (size_t)WSTRIDE, out);
}